// round 14
// baseline (speedup 1.0000x reference)
#include <cuda_runtime.h>

#define NX 1024
#define NY 1024
#define NB 8
#define CH (NX*NY)
#define XBLKS (NY*2)            // 2 blocks per row
#define NBLOCKS (XBLKS*NB)      // 16384
#define NPTS 8388608.0

// Physics constants
#define PR     0.71f
#define RA_PR  710.0f
#define HA2_PR 71.0f
#define PR_DA  7.1f
#define DIFF_C 1.6666666666666667f
#define QQ     0.1f
#define DTINV  100.0f

__device__ double g_partials[NBLOCKS];

// 2-point channel derivative set. E0..E5 = values at gx-2 .. gx+3.
struct CD2 { float v[2], dx[2], dxx[2], dy[2], dyy[2]; };

__device__ __forceinline__ void chan2(const float* __restrict__ ch,
    int y, int gx, bool lE, bool rE,
    int rM, int rP, float s1,
    int rA, int rB, float cA, float cC, float cB,
    CD2& d)
{
    const float* rowp = ch + (size_t)y * NX;
    float2 c = *(const float2*)(rowp + gx);
    float2 l = make_float2(0.0f, 0.0f), r = make_float2(0.0f, 0.0f);
    if (!lE) l = *(const float2*)(rowp + gx - 2);
    if (!rE) r = *(const float2*)(rowp + gx + 2);
    float2 m  = *(const float2*)(ch + (size_t)rM * NX + gx);
    float2 p  = *(const float2*)(ch + (size_t)rP * NX + gx);
    float2 a  = *(const float2*)(ch + (size_t)rA * NX + gx);
    float2 bb = *(const float2*)(ch + (size_t)rB * NX + gx);

    float E0 = l.x, E1 = l.y, E2 = c.x, E3 = c.y, E4 = r.x, E5 = r.y;
    if (lE) {              // gx == 0: points i=0,1
        d.dx[0]  = E3 - E2;
        d.dx[1]  = 0.5f * (E4 - E2);
        d.dxx[0] = 0.5f * E4 - E3 + 0.5f * E2;
        d.dxx[1] = 0.25f * E5 - 0.75f * E3 + 0.5f * E2;
    } else if (rE) {       // gx == NX-2: points i=NX-2,NX-1
        d.dx[0]  = 0.5f * (E3 - E1);
        d.dx[1]  = E3 - E2;
        d.dxx[0] = 0.5f * E3 - 0.75f * E2 + 0.25f * E0;
        d.dxx[1] = 0.5f * E3 - E2 + 0.5f * E1;
    } else {               // interior
        d.dx[0]  = 0.5f * (E3 - E1);
        d.dx[1]  = 0.5f * (E4 - E2);
        d.dxx[0] = 0.25f * (E4 - 2.0f * E2 + E0);
        d.dxx[1] = 0.25f * (E5 - 2.0f * E3 + E1);
    }
    d.v[0] = E2;  d.v[1] = E3;
    d.dy[0] = s1 * (p.x - m.x);
    d.dy[1] = s1 * (p.y - m.y);
    d.dyy[0] = cA * a.x + cC * E2 + cB * bb.x;
    d.dyy[1] = cA * a.y + cC * E3 + cB * bb.y;
}

__global__ __launch_bounds__(256)
void physics_loss_kernel(const float* __restrict__ fno, const float* __restrict__ fne)
{
    const int tid  = threadIdx.x;
    const int xb   = blockIdx.x;            // row*2 + half
    const int y    = xb >> 1;
    const int b    = blockIdx.y;
    const int gx   = ((xb & 1) << 9) + tid * 2;   // 2 points per thread
    const bool lE  = (gx == 0);
    const bool rE  = (gx == NX - 2);

    const int   rM = (y > 0) ? y - 1 : 0;
    const int   rP = (y < NY - 1) ? y + 1 : NY - 1;
    const float s1 = (y == 0 || y == NY - 1) ? 1.0f : 0.5f;

    int rA, rB; float cA, cC, cB;
    if      (y == 0)      { rA = 2;      cA = 0.5f;  cC = 0.5f;   rB = 1;      cB = -1.0f; }
    else if (y == 1)      { rA = 0;      cA = 0.5f;  cC = -0.75f; rB = 3;      cB = 0.25f; }
    else if (y == NY - 2) { rA = NY - 4; cA = 0.25f; cC = -0.75f; rB = NY - 1; cB = 0.5f;  }
    else if (y == NY - 1) { rA = NY - 3; cA = 0.5f;  cC = 0.5f;   rB = NY - 2; cB = -1.0f; }
    else                  { rA = y - 2;  cA = 0.25f; cC = -0.5f;  rB = y + 2;  cB = 0.25f; }

    const size_t base = (size_t)b * 4 * CH;
    const size_t rowo = (size_t)y * NX + gx;

    // f_now fields (U, V, T)
    float2 uo = *(const float2*)(fno + base + 0 * (size_t)CH + rowo);
    float2 vo = *(const float2*)(fno + base + 1 * (size_t)CH + rowo);
    float2 to = *(const float2*)(fno + base + 2 * (size_t)CH + rowo);
    float Uo[2] = {uo.x, uo.y};
    float Vo[2] = {vo.x, vo.y};
    float To[2] = {to.x, to.y};

    float cont[2], resx[2], resy[2], rest[2];

    CD2 D;
    // ---- U_next ----
    chan2(fne + base + 0 * (size_t)CH, y, gx, lE, rE, rM, rP, s1, rA, rB, cA, cC, cB, D);
#pragma unroll
    for (int j = 0; j < 2; j++) {
        float Un = D.v[j];
        cont[j] = D.dx[j];
        resx[j] = (Un - Uo[j]) * DTINV + Un * D.dx[j] + Vo[j] * D.dy[j]
                  - PR * (D.dxx[j] + D.dyy[j]) + PR_DA * Un;
    }
    // ---- V_next ----
    chan2(fne + base + 1 * (size_t)CH, y, gx, lE, rE, rM, rP, s1, rA, rB, cA, cC, cB, D);
#pragma unroll
    for (int j = 0; j < 2; j++) {
        float Vn = D.v[j];
        cont[j] += D.dy[j];
        resy[j] = (Vn - Vo[j]) * DTINV + Uo[j] * D.dx[j] + Vn * D.dy[j]
                  - PR * (D.dxx[j] + D.dyy[j]) + (HA2_PR + PR_DA) * Vn;
    }
    // ---- T_next ----
    chan2(fne + base + 2 * (size_t)CH, y, gx, lE, rE, rM, rP, s1, rA, rB, cA, cC, cB, D);
#pragma unroll
    for (int j = 0; j < 2; j++) {
        float Tn = D.v[j];
        resy[j] -= RA_PR * Tn;
        rest[j] = (Tn - To[j]) * DTINV + Uo[j] * D.dx[j] + Vo[j] * D.dy[j]
                  - DIFF_C * (D.dxx[j] + D.dyy[j]) - QQ * Tn;
    }
    // ---- P_next (dx, dy only) ----
    {
        const float* Pc = fne + base + 3 * (size_t)CH;
        const float* rowp = Pc + (size_t)y * NX;
        float2 c = *(const float2*)(rowp + gx);
        float2 l = make_float2(0.0f, 0.0f), r = make_float2(0.0f, 0.0f);
        if (!lE) l = *(const float2*)(rowp + gx - 2);
        if (!rE) r = *(const float2*)(rowp + gx + 2);
        float2 m = *(const float2*)(Pc + (size_t)rM * NX + gx);
        float2 p = *(const float2*)(Pc + (size_t)rP * NX + gx);
        float E1 = l.y, E2 = c.x, E3 = c.y, E4 = r.x;
        float pdx0 = lE ? (E3 - E2) : 0.5f * (E3 - E1);
        float pdx1 = rE ? (E3 - E2) : 0.5f * (E4 - E2);
        resx[0] += pdx0;
        resx[1] += pdx1;
        resy[0] += s1 * (p.x - m.x);
        resy[1] += s1 * (p.y - m.y);
    }

    float acc = 0.0f;
#pragma unroll
    for (int j = 0; j < 2; j++) {
        acc += cont[j] * cont[j] + resx[j] * resx[j]
             + resy[j] * resy[j] + rest[j] * rest[j];
    }

    // warp + block reduction, ONE plain store (R12-proven clean tail)
#pragma unroll
    for (int o = 16; o > 0; o >>= 1) acc += __shfl_xor_sync(0xFFFFFFFFu, acc, o);

    __shared__ float ws[8];
    if ((tid & 31) == 0) ws[tid >> 5] = acc;
    __syncthreads();
    if (tid == 0) {
        double s = 0.0;
#pragma unroll
        for (int k = 0; k < 8; k++) s += (double)ws[k];
        g_partials[(size_t)blockIdx.y * XBLKS + xb] = s;
    }
}

__global__ __launch_bounds__(1024)
void finalize_kernel(float* __restrict__ out)
{
    const int tid = threadIdx.x;
    double v = 0.0;
#pragma unroll
    for (int k = 0; k < NBLOCKS / 1024; k++)   // 16 loads/thread
        v += g_partials[tid + k * 1024];
#pragma unroll
    for (int o = 16; o > 0; o >>= 1)
        v += __shfl_xor_sync(0xFFFFFFFFu, v, o);
    __shared__ double ws[32];
    if ((tid & 31) == 0) ws[tid >> 5] = v;
    __syncthreads();
    if (tid == 0) {
        double s = 0.0;
#pragma unroll
        for (int k = 0; k < 32; k++) s += ws[k];
        double t = s * 1e-4 / NPTS;
        if (t < 1e-10) t = 1e-10;
        if (t > 1.0)   t = 1.0;
        out[0] = (float)t;
    }
}

extern "C" void kernel_launch(void* const* d_in, const int* in_sizes, int n_in,
                              void* d_out, int out_size)
{
    const float* f_now  = (const float*)d_in[0];
    const float* f_next = (const float*)d_in[1];

    dim3 grid(XBLKS, NB);
    physics_loss_kernel<<<grid, 256>>>(f_now, f_next);
    finalize_kernel<<<1, 1024>>>((float*)d_out);
}

// round 15
// speedup vs baseline: 1.5770x; 1.5770x over previous
#include <cuda_runtime.h>

// Problem constants
#define NX 1024
#define NY 1024
#define NBATCH 8
#define CH (1024*1024)           // channel stride
#define NPTS 8388608.0           // 8*1024*1024 (mean denominator)

// Physics constants (match reference exactly)
#define PR     0.71f
#define RA_PR  710.0f            // RA*PR = 1000*0.71
#define HA2_PR 71.0f             // HA^2*PR = 100*0.71
#define PR_DA  7.1f              // PR/DA = 0.71/0.1
#define DIFF_C 1.6666666666666667f  // 1 + 4*0.5/3
#define QQ     0.1f
#define DTINV  (1.0f/0.01f)

__device__ double g_acc;   // zero-initialized at load; finalize resets after read

// tgrad along x at global index i, window W[12] covers x0-4 .. x0+7, center at W[j+4]
__device__ __forceinline__ float d1x(const float* W, int j, int i) {
    if (i == 0)      return W[5] - W[4];
    if (i == NX - 1) return W[j + 4] - W[j + 3];
    return 0.5f * (W[j + 5] - W[j + 3]);
}

// tgrad(tgrad(f,x),x) at index i (edge forms derived from composing tgrad)
__device__ __forceinline__ float d2x(const float* W, int j, int i) {
    if (i == 0)      return 0.5f * W[6] - W[5] + 0.5f * W[4];
    if (i == 1)      return 0.25f * W[7] - 0.75f * W[5] + 0.5f * W[4];
    if (i == NX - 2) return 0.5f * W[j + 5] - 0.75f * W[j + 4] + 0.25f * W[j + 2];
    if (i == NX - 1) return 0.5f * W[j + 4] - W[j + 3] + 0.5f * W[j + 2];
    return 0.25f * (W[j + 6] - 2.0f * W[j + 4] + W[j + 2]);
}

// Load 12-float x-window around this thread's 4 points from row `row`
__device__ __forceinline__ void load_window(const float* __restrict__ row, int tid, int x0, float* W) {
    float4 c = *(const float4*)(row + x0);
    W[4] = c.x; W[5] = c.y; W[6] = c.z; W[7] = c.w;
    if (tid > 0) {
        float4 l = *(const float4*)(row + x0 - 4);
        W[0] = l.x; W[1] = l.y; W[2] = l.z; W[3] = l.w;
    } else { W[0] = W[1] = W[2] = W[3] = 0.0f; }
    if (tid < 255) {
        float4 r = *(const float4*)(row + x0 + 4);
        W[8] = r.x; W[9] = r.y; W[10] = r.z; W[11] = r.w;
    } else { W[8] = W[9] = W[10] = W[11] = 0.0f; }
}

// Full derivative set for one f_next channel at (y, x0..x0+3)
struct Deriv { float v[4], dx[4], dy[4], dxx[4], dyy[4]; };

__device__ __forceinline__ void full_derivs(
    const float* __restrict__ ch, int tid, int y, int x0,
    int rM, int rP, float s1,
    int rA, int rB, float cA, float cC, float cB,
    Deriv& d)
{
    float W[12];
    load_window(ch + (size_t)y * NX, tid, x0, W);
    float4 m  = *(const float4*)(ch + (size_t)rM * NX + x0);
    float4 p  = *(const float4*)(ch + (size_t)rP * NX + x0);
    float4 a  = *(const float4*)(ch + (size_t)rA * NX + x0);
    float4 bb = *(const float4*)(ch + (size_t)rB * NX + x0);
    float mm[4]  = {m.x,  m.y,  m.z,  m.w};
    float pp[4]  = {p.x,  p.y,  p.z,  p.w};
    float aa[4]  = {a.x,  a.y,  a.z,  a.w};
    float bbv[4] = {bb.x, bb.y, bb.z, bb.w};
#pragma unroll
    for (int j = 0; j < 4; j++) {
        int i = x0 + j;
        d.v[j]   = W[j + 4];
        d.dx[j]  = d1x(W, j, i);
        d.dxx[j] = d2x(W, j, i);
        d.dy[j]  = s1 * (pp[j] - mm[j]);
        d.dyy[j] = cA * aa[j] + cC * W[j + 4] + cB * bbv[j];
    }
}

__global__ __launch_bounds__(256)
void physics_loss_kernel(const float* __restrict__ fno, const float* __restrict__ fne)
{
    const int tid = threadIdx.x;
    const int y   = blockIdx.x;
    const int b   = blockIdx.y;
    const int x0  = tid * 4;

    // y-gradient (first derivative) rows + scale
    const int   rM = (y > 0) ? y - 1 : 0;
    const int   rP = (y < NY - 1) ? y + 1 : NY - 1;
    const float s1 = (y == 0 || y == NY - 1) ? 1.0f : 0.5f;

    // y second-derivative rows + coefficients: d2y = cA*f[rA] + cC*f[y] + cB*f[rB]
    int rA, rB; float cA, cC, cB;
    if      (y == 0)      { rA = 2;      cA = 0.5f;  cC = 0.5f;   rB = 1;      cB = -1.0f; }
    else if (y == 1)      { rA = 0;      cA = 0.5f;  cC = -0.75f; rB = 3;      cB = 0.25f; }
    else if (y == NY - 2) { rA = NY - 4; cA = 0.25f; cC = -0.75f; rB = NY - 1; cB = 0.5f;  }
    else if (y == NY - 1) { rA = NY - 3; cA = 0.5f;  cC = 0.5f;   rB = NY - 2; cB = -1.0f; }
    else                  { rA = y - 2;  cA = 0.25f; cC = -0.5f;  rB = y + 2;  cB = 0.25f; }

    const size_t base = (size_t)b * 4 * CH;
    const size_t rowo = (size_t)y * NX + x0;

    // f_now fields (U, V, T) — single float4 each
    float4 uo4 = *(const float4*)(fno + base + 0 * (size_t)CH + rowo);
    float4 vo4 = *(const float4*)(fno + base + 1 * (size_t)CH + rowo);
    float4 to4 = *(const float4*)(fno + base + 2 * (size_t)CH + rowo);
    float Uo[4] = {uo4.x, uo4.y, uo4.z, uo4.w};
    float Vo[4] = {vo4.x, vo4.y, vo4.z, vo4.w};
    float To[4] = {to4.x, to4.y, to4.z, to4.w};

    float cont[4], resx[4], resy[4], rest[4];

    Deriv D;
    // ---- U_next ----
    full_derivs(fne + base + 0 * (size_t)CH, tid, y, x0, rM, rP, s1, rA, rB, cA, cC, cB, D);
#pragma unroll
    for (int j = 0; j < 4; j++) {
        float Un = D.v[j];
        cont[j] = D.dx[j];
        resx[j] = (Un - Uo[j]) * DTINV + Un * D.dx[j] + Vo[j] * D.dy[j]
                  - PR * (D.dxx[j] + D.dyy[j]) + PR_DA * Un;
    }
    // ---- V_next ----
    full_derivs(fne + base + 1 * (size_t)CH, tid, y, x0, rM, rP, s1, rA, rB, cA, cC, cB, D);
#pragma unroll
    for (int j = 0; j < 4; j++) {
        float Vn = D.v[j];
        cont[j] += D.dy[j];
        resy[j] = (Vn - Vo[j]) * DTINV + Uo[j] * D.dx[j] + Vn * D.dy[j]
                  - PR * (D.dxx[j] + D.dyy[j]) + (HA2_PR + PR_DA) * Vn;
    }
    // ---- T_next ----
    full_derivs(fne + base + 2 * (size_t)CH, tid, y, x0, rM, rP, s1, rA, rB, cA, cC, cB, D);
#pragma unroll
    for (int j = 0; j < 4; j++) {
        float Tn = D.v[j];
        resy[j] -= RA_PR * Tn;
        rest[j] = (Tn - To[j]) * DTINV + Uo[j] * D.dx[j] + Vo[j] * D.dy[j]
                  - DIFF_C * (D.dxx[j] + D.dyy[j]) - QQ * Tn;
    }
    // ---- P_next (dx, dy only) ----
    {
        const float* Pc = fne + base + 3 * (size_t)CH;
        float W[12];
        load_window(Pc + (size_t)y * NX, tid, x0, W);
        float4 m = *(const float4*)(Pc + (size_t)rM * NX + x0);
        float4 p = *(const float4*)(Pc + (size_t)rP * NX + x0);
        float mm[4] = {m.x, m.y, m.z, m.w};
        float pp[4] = {p.x, p.y, p.z, p.w};
#pragma unroll
        for (int j = 0; j < 4; j++) {
            int i = x0 + j;
            resx[j] += d1x(W, j, i);          // +dP/dx
            resy[j] += s1 * (pp[j] - mm[j]);  // +dP/dy
        }
    }

    // accumulate squared residuals
    float acc = 0.0f;
#pragma unroll
    for (int j = 0; j < 4; j++) {
        acc += cont[j] * cont[j] + resx[j] * resx[j]
             + resy[j] * resy[j] + rest[j] * rest[j];
    }

    // warp reduce
#pragma unroll
    for (int o = 16; o > 0; o >>= 1) acc += __shfl_xor_sync(0xFFFFFFFFu, acc, o);

    __shared__ float ws[8];
    if ((tid & 31) == 0) ws[tid >> 5] = acc;
    __syncthreads();
    if (tid == 0) {
        float s = 0.0f;
#pragma unroll
        for (int k = 0; k < 8; k++) s += ws[k];
        atomicAdd(&g_acc, (double)s);
    }
}

__global__ void finalize_kernel(float* out)
{
    double t = g_acc * 1e-4 / NPTS;
    if (t < 1e-10) t = 1e-10;
    if (t > 1.0)   t = 1.0;
    out[0] = (float)t;
    g_acc = 0.0;   // reset for next graph replay (stream-ordered before next main)
}

extern "C" void kernel_launch(void* const* d_in, const int* in_sizes, int n_in,
                              void* d_out, int out_size)
{
    const float* f_now  = (const float*)d_in[0];
    const float* f_next = (const float*)d_in[1];

    dim3 grid(NY, NBATCH);  // one block per (row, batch)
    physics_loss_kernel<<<grid, 256>>>(f_now, f_next);
    finalize_kernel<<<1, 1>>>((float*)d_out);
}

// round 16
// speedup vs baseline: 1.6332x; 1.0357x over previous
#include <cuda_runtime.h>

#define NX 1024
#define NY 1024
#define NBATCH 8
#define CH (1024*1024)
#define NPTS 8388608.0

// Physics constants
#define PR     0.71f
#define RA_PR  710.0f
#define HA2_PR 71.0f
#define PR_DA  7.1f
#define DIFF_C 1.6666666666666667f
#define QQ     0.1f
#define DTINV  (1.0f/0.01f)

__device__ double g_acc;   // zero at load; finalize resets after read (replay-safe)

// tgrad along x at global index i, window W[12] covers x0-4 .. x0+7, center at W[j+4]
__device__ __forceinline__ float d1x(const float* W, int j, int i) {
    if (i == 0)      return W[5] - W[4];
    if (i == NX - 1) return W[j + 4] - W[j + 3];
    return 0.5f * (W[j + 5] - W[j + 3]);
}

__device__ __forceinline__ float d2x(const float* W, int j, int i) {
    if (i == 0)      return 0.5f * W[6] - W[5] + 0.5f * W[4];
    if (i == 1)      return 0.25f * W[7] - 0.75f * W[5] + 0.5f * W[4];
    if (i == NX - 2) return 0.5f * W[j + 5] - 0.75f * W[j + 4] + 0.25f * W[j + 2];
    if (i == NX - 1) return 0.5f * W[j + 4] - W[j + 3] + 0.5f * W[j + 2];
    return 0.25f * (W[j + 6] - 2.0f * W[j + 4] + W[j + 2]);
}

__device__ __forceinline__ void load_window(const float* __restrict__ row, int tid, int x0, float* W) {
    float4 c = *(const float4*)(row + x0);
    W[4] = c.x; W[5] = c.y; W[6] = c.z; W[7] = c.w;
    if (tid > 0) {
        float4 l = *(const float4*)(row + x0 - 4);
        W[0] = l.x; W[1] = l.y; W[2] = l.z; W[3] = l.w;
    } else { W[0] = W[1] = W[2] = W[3] = 0.0f; }
    if (tid < 255) {
        float4 r = *(const float4*)(row + x0 + 4);
        W[8] = r.x; W[9] = r.y; W[10] = r.z; W[11] = r.w;
    } else { W[8] = W[9] = W[10] = W[11] = 0.0f; }
}

struct Deriv { float v[4], dx[4], dy[4], dxx[4], dyy[4]; };

__device__ __forceinline__ void full_derivs(
    const float* __restrict__ ch, int tid, int y, int x0,
    int rM, int rP, float s1,
    int rA, int rB, float cA, float cC, float cB,
    Deriv& d)
{
    float W[12];
    load_window(ch + (size_t)y * NX, tid, x0, W);
    float4 m  = *(const float4*)(ch + (size_t)rM * NX + x0);
    float4 p  = *(const float4*)(ch + (size_t)rP * NX + x0);
    float4 a  = *(const float4*)(ch + (size_t)rA * NX + x0);
    float4 bb = *(const float4*)(ch + (size_t)rB * NX + x0);
    const float* M  = (const float*)&m;  const float* P_ = (const float*)&p;
    const float* A  = (const float*)&a;  const float* B_ = (const float*)&bb;
#pragma unroll
    for (int j = 0; j < 4; j++) {
        int i = x0 + j;
        d.v[j]   = W[j + 4];
        d.dx[j]  = d1x(W, j, i);
        d.dxx[j] = d2x(W, j, i);
        d.dy[j]  = s1 * (P_[j] - M[j]);
        d.dyy[j] = cA * A[j] + cC * W[j + 4] + cB * B_[j];
    }
}

__global__ __launch_bounds__(256, 5)
void physics_loss_kernel(const float* __restrict__ fno, const float* __restrict__ fne)
{
    const int tid = threadIdx.x;
    const int y   = blockIdx.x;
    const int b   = blockIdx.y;
    const int x0  = tid * 4;

    const int   rM = (y > 0) ? y - 1 : 0;
    const int   rP = (y < NY - 1) ? y + 1 : NY - 1;
    const float s1 = (y == 0 || y == NY - 1) ? 1.0f : 0.5f;

    int rA, rB; float cA, cC, cB;
    if      (y == 0)      { rA = 2;      cA = 0.5f;  cC = 0.5f;   rB = 1;      cB = -1.0f; }
    else if (y == 1)      { rA = 0;      cA = 0.5f;  cC = -0.75f; rB = 3;      cB = 0.25f; }
    else if (y == NY - 2) { rA = NY - 4; cA = 0.25f; cC = -0.75f; rB = NY - 1; cB = 0.5f;  }
    else if (y == NY - 1) { rA = NY - 3; cA = 0.5f;  cC = 0.5f;   rB = NY - 2; cB = -1.0f; }
    else                  { rA = y - 2;  cA = 0.25f; cC = -0.5f;  rB = y + 2;  cB = 0.25f; }

    const size_t base = (size_t)b * 4 * CH;
    const size_t rowo = (size_t)y * NX + x0;

    float acc = 0.0f;

    // ---- P pass first: pdx, pdy (consumed by U and V passes) ----
    float pdx[4], pdy[4];
    {
        const float* Pc = fne + base + 3 * (size_t)CH;
        float W[12];
        load_window(Pc + (size_t)y * NX, tid, x0, W);
        float4 m = *(const float4*)(Pc + (size_t)rM * NX + x0);
        float4 p = *(const float4*)(Pc + (size_t)rP * NX + x0);
        const float* M = (const float*)&m; const float* P_ = (const float*)&p;
#pragma unroll
        for (int j = 0; j < 4; j++) {
            pdx[j] = d1x(W, j, x0 + j);
            pdy[j] = s1 * (P_[j] - M[j]);
        }
    }

    // f_now U, V only (T loaded inside T pass to shrink live range)
    float4 uo4 = *(const float4*)(fno + base + 0 * (size_t)CH + rowo);
    float4 vo4 = *(const float4*)(fno + base + 1 * (size_t)CH + rowo);
    float Uo[4] = {uo4.x, uo4.y, uo4.z, uo4.w};
    float Vo[4] = {vo4.x, vo4.y, vo4.z, vo4.w};

    float cont[4], resy[4];

    Deriv D;
    // ---- U pass: resx squared & freed (consumes pdx); keep cont ----
    full_derivs(fne + base + 0 * (size_t)CH, tid, y, x0, rM, rP, s1, rA, rB, cA, cC, cB, D);
#pragma unroll
    for (int j = 0; j < 4; j++) {
        float Un = D.v[j];
        float resx = (Un - Uo[j]) * DTINV + Un * D.dx[j] + Vo[j] * D.dy[j]
                     + pdx[j] - PR * (D.dxx[j] + D.dyy[j]) + PR_DA * Un;
        acc += resx * resx;
        cont[j] = D.dx[j];
    }
    // ---- V pass: cont squared & freed; resy started (consumes pdy) ----
    full_derivs(fne + base + 1 * (size_t)CH, tid, y, x0, rM, rP, s1, rA, rB, cA, cC, cB, D);
#pragma unroll
    for (int j = 0; j < 4; j++) {
        float Vn = D.v[j];
        float cj = cont[j] + D.dy[j];
        acc += cj * cj;
        resy[j] = (Vn - Vo[j]) * DTINV + Uo[j] * D.dx[j] + Vn * D.dy[j]
                  + pdy[j] - PR * (D.dxx[j] + D.dyy[j]) + (HA2_PR + PR_DA) * Vn;
    }
    // ---- T pass: resy & rest finished ----
    full_derivs(fne + base + 2 * (size_t)CH, tid, y, x0, rM, rP, s1, rA, rB, cA, cC, cB, D);
    {
        float4 to4 = *(const float4*)(fno + base + 2 * (size_t)CH + rowo);
        const float* To = (const float*)&to4;
#pragma unroll
        for (int j = 0; j < 4; j++) {
            float Tn = D.v[j];
            float ry = resy[j] - RA_PR * Tn;
            acc += ry * ry;
            float rest = (Tn - To[j]) * DTINV + Uo[j] * D.dx[j] + Vo[j] * D.dy[j]
                         - DIFF_C * (D.dxx[j] + D.dyy[j]) - QQ * Tn;
            acc += rest * rest;
        }
    }

    // warp + block reduce, one atomicAdd per CTA (R15-proven tail)
#pragma unroll
    for (int o = 16; o > 0; o >>= 1) acc += __shfl_xor_sync(0xFFFFFFFFu, acc, o);

    __shared__ float ws[8];
    if ((tid & 31) == 0) ws[tid >> 5] = acc;
    __syncthreads();
    if (tid == 0) {
        float s = 0.0f;
#pragma unroll
        for (int k = 0; k < 8; k++) s += ws[k];
        atomicAdd(&g_acc, (double)s);
    }
}

__global__ void finalize_kernel(float* out)
{
    double t = g_acc * 1e-4 / NPTS;
    if (t < 1e-10) t = 1e-10;
    if (t > 1.0)   t = 1.0;
    out[0] = (float)t;
    g_acc = 0.0;   // reset for next graph replay
}

extern "C" void kernel_launch(void* const* d_in, const int* in_sizes, int n_in,
                              void* d_out, int out_size)
{
    const float* f_now  = (const float*)d_in[0];
    const float* f_next = (const float*)d_in[1];

    dim3 grid(NY, NBATCH);
    physics_loss_kernel<<<grid, 256>>>(f_now, f_next);
    finalize_kernel<<<1, 1>>>((float*)d_out);
}